// round 8
// baseline (speedup 1.0000x reference)
#include <cuda_runtime.h>
#include <math.h>
#include <stdint.h>

#define M_MAX   360448
#define NMAX    8100000
#define PD      614
#define MAXV    1024
#define QFPS    410
#define MAXPTS  32
#define CAP     128
#define LCAP    8192
#define HBINS   2048
#define NB      148
#define NT      256
#define CPT     10      // NB*NT*CPT = 378880 >= M_MAX
#define NSTEPS  (QFPS - 1)

__device__ int                g_count[M_MAX];
__device__ int                g_keys[NMAX];
__device__ int                g_newindex[M_MAX];
__device__ unsigned char      g_valid[M_MAX];
__device__ int                g_hist[HBINS];
__device__ int                g_T;
__device__ unsigned int       g_list[LCAP];
__device__ int                g_listn;
__device__ int                g_sel[MAXV];
__device__ int                g_start;
__device__ unsigned long long g_slot[NSTEPS * NB];   // data-is-flag barrier slots
__device__ int                g_ctr[MAXV];
__device__ int                g_buf[MAXV * CAP];

struct P9 { float lox, loy, loz, vx, vy, vz; int gx, gy, gz, M; };

__device__ __forceinline__ P9 mkp(const float* vs, const float* cr) {
    P9 p;
    p.lox = cr[0]; p.loy = cr[1]; p.loz = cr[2];
    p.vx = vs[0]; p.vy = vs[1]; p.vz = vs[2];
    p.gx = (int)floorf(__fdiv_rn(__fsub_rn(cr[3], cr[0]), vs[0]));
    p.gy = (int)floorf(__fdiv_rn(__fsub_rn(cr[4], cr[1]), vs[1]));
    p.gz = (int)floorf(__fdiv_rn(__fsub_rn(cr[5], cr[2]), vs[2]));
    p.M = p.gx * p.gy * p.gz;
    return p;
}

// centroid: STRICT separate mul + add (locked — bit-exact vs reference)
__device__ __forceinline__ void decode_centroid(int key, const P9& p,
                                                float& cx, float& cy, float& cz) {
    int gyz = p.gy * p.gz;
    int ix = key / gyz;
    int r  = key - ix * gyz;
    int iy = r / p.gz;
    int iz = r - iy * p.gz;
    cx = __fadd_rn(__fmul_rn((float)ix, p.vx), p.lox);
    cy = __fadd_rn(__fmul_rn((float)iy, p.vy), p.loy);
    cz = __fadd_rn(__fmul_rn((float)iz, p.vz), p.loz);
}

// ---------------- reset ----------------
__global__ void k_reset() {
    int i = blockIdx.x * blockDim.x + threadIdx.x;
    if (i < M_MAX) { g_count[i] = 0; g_newindex[i] = -1; }
    if (i < HBINS) g_hist[i] = 0;
    if (i < LCAP)  g_list[i] = 0xFFFFFFFFu;
    if (i < MAXV)  g_ctr[i] = 0;
    if (i < NSTEPS * NB) g_slot[i] = 0ull;
    if (i == 0) { g_listn = 0; g_start = 0x7FFFFFFF; g_T = 1; }
}

// ---------------- pass 1: keys + histogram ----------------
__global__ void k_points(const float* __restrict__ pts, const float* vs,
                         const float* cr, int N) {
    int i = blockIdx.x * blockDim.x + threadIdx.x;
    if (i >= N || i >= NMAX) return;
    P9 p = mkp(vs, cr);
    float x = pts[3 * i + 0];
    float y = pts[3 * i + 1];
    float z = pts[3 * i + 2];
    int vxi = (int)floorf(__fdiv_rn(__fsub_rn(x, p.lox), p.vx));
    int vyi = (int)floorf(__fdiv_rn(__fsub_rn(y, p.loy), p.vy));
    int vzi = (int)floorf(__fdiv_rn(__fsub_rn(z, p.loz), p.vz));
    vxi = min(max(vxi, 0), p.gx - 1);
    vyi = min(max(vyi, 0), p.gy - 1);
    vzi = min(max(vzi, 0), p.gz - 1);
    int key = (vxi * p.gy + vyi) * p.gz + vzi;
    g_keys[i] = key;
    atomicAdd(&g_count[key], 1);
}

// ---------------- count histogram ----------------
__global__ void k_hist(const float* vs, const float* cr) {
    int k = blockIdx.x * blockDim.x + threadIdx.x;
    P9 p = mkp(vs, cr);
    if (k >= p.M) return;
    int c = g_count[k];
    if (c > 0) atomicAdd(&g_hist[min(c, HBINS - 1)], 1);
}

// ---------------- threshold T: 614th largest count (parallel suffix scan) ----------------
__global__ void k_thresh() {
    int t = threadIdx.x;            // 0..1023, each owns 2 reversed bins
    int c1 = 2047 - 2 * t;          // higher count bin
    int c2 = 2046 - 2 * t;          // lower count bin
    int a0 = g_hist[c1];
    int a1 = (c2 >= 0) ? g_hist[c2] : 0;
    int ts = a0 + a1;
    int lane = t & 31, wid = t >> 5;
    // inclusive warp scan of ts
    int v = ts;
#pragma unroll
    for (int o = 1; o < 32; o <<= 1) {
        int u = __shfl_up_sync(0xFFFFFFFFu, v, o);
        if (lane >= o) v += u;
    }
    __shared__ int wsum[32];
    if (lane == 31) wsum[wid] = v;
    __syncthreads();
    if (wid == 0) {
        int w = wsum[lane];
#pragma unroll
        for (int o = 1; o < 32; o <<= 1) {
            int u = __shfl_up_sync(0xFFFFFFFFu, w, o);
            if (lane >= o) w += u;
        }
        wsum[lane] = w;
    }
    __syncthreads();
    int incl = v + (wid > 0 ? wsum[wid - 1] : 0);
    int E = incl - ts;              // exclusive prefix = suffix(c1+1)
    int s1 = E + a0;                // suffix(c1)
    int s2 = E + a0 + a1;           // suffix(c2)
    if (c1 >= 1 && s1 >= PD && E < PD)  g_T = c1;
    if (c2 >= 1 && s2 >= PD && s1 < PD) g_T = c2;
    if (t == 1023 && s1 < PD) g_T = 1;   // total valid < PD fallback
}

// ---------------- collect keys with count >= T ----------------
__global__ void k_collect(const float* vs, const float* cr) {
    int k = blockIdx.x * blockDim.x + threadIdx.x;
    P9 p = mkp(vs, cr);
    if (k >= p.M) return;
    int c = g_count[k];
    if (c >= g_T) {
        int pos = atomicAdd(&g_listn, 1);
        if (pos < LCAP) {
            unsigned cc = (unsigned)min(c, HBINS - 1);
            g_list[pos] = (((unsigned)(HBINS - 1) - cc) << 19) | (unsigned)k;
        }
    }
}

// ---------------- sort candidates, take top PD in (count desc, key asc) ----------------
__global__ void k_sorttop() {
    __shared__ unsigned int s[LCAP];
    int tid = threadIdx.x;
    for (int t = tid; t < LCAP; t += blockDim.x) s[t] = g_list[t];
    __syncthreads();
    for (int ks = 2; ks <= LCAP; ks <<= 1) {
        for (int j = ks >> 1; j > 0; j >>= 1) {
            for (int t = tid; t < LCAP; t += blockDim.x) {
                int ixj = t ^ j;
                if (ixj > t) {
                    bool up = ((t & ks) == 0);
                    unsigned a = s[t], b = s[ixj];
                    if ((a > b) == up) { s[t] = b; s[ixj] = a; }
                }
            }
            __syncthreads();
        }
    }
    if (tid < PD) {
        int key = (int)(s[tid] & 0x7FFFFu);
        g_sel[tid] = key;
        g_newindex[key] = tid;
    }
}

// ---------------- FPS validity mask + start (smallest remaining key) ----------------
__global__ void k_prep(const float* vs, const float* cr) {
    int k = blockIdx.x * blockDim.x + threadIdx.x;
    P9 p = mkp(vs, cr);
    if (k >= p.M) return;
    int v = (g_count[k] > 0 && g_newindex[k] < 0) ? 1 : 0;
    g_valid[k] = (unsigned char)v;
    if (v) atomicMin(&g_start, k);
}

// ---------------- persistent FPS kernel: 409 steps, data-is-flag barrier ----------------
__global__ __launch_bounds__(NT) void k_fps(const float* vs, const float* cr) {
    P9 p = mkp(vs, cr);
    int tid = threadIdx.x, b = blockIdx.x;
    int base = b * (NT * CPT);

    float dist[CPT], cx[CPT], cy[CPT], cz[CPT];
    unsigned vm = 0;
#pragma unroll
    for (int j = 0; j < CPT; j++) {
        int k = base + j * NT + tid;
        float X = 0.f, Y = 0.f, Z = 0.f;
        int ok = 0;
        if (k < p.M) {
            ok = g_valid[k];
            decode_centroid(k, p, X, Y, Z);
        }
        cx[j] = X; cy[j] = Y; cz[j] = Z;
        dist[j] = __int_as_float(0x7f800000);  // +inf
        vm |= (ok ? 1u : 0u) << j;
    }

    __shared__ unsigned long long swarp[NT / 32];
    __shared__ int s_last;
    int last = g_start;
    if (b == 0 && tid == 0) g_sel[PD] = g_start;

    for (int s = 0; s < NSTEPS; s++) {
        float lx, ly, lz;
        decode_centroid(last, p, lx, ly, lz);

        unsigned long long best = 0ull;
#pragma unroll
        for (int j = 0; j < CPT; j++) {
            float dx = __fsub_rn(cx[j], lx);
            float dy = __fsub_rn(cy[j], ly);
            float dz = __fsub_rn(cz[j], lz);
            // locked formula: fma(dz,dz, fma(dx,dx, rn(dy*dy)))
            float d = __fmaf_rn(dz, dz, __fmaf_rn(dx, dx, __fmul_rn(dy, dy)));
            float nd = fminf(dist[j], d);
            dist[j] = nd;
            if ((vm >> j) & 1u) {
                int k = base + j * NT + tid;
                unsigned long long pk =
                    ((unsigned long long)__float_as_uint(nd) << 32) |
                    (unsigned long long)(0xFFFFFFFFu - (unsigned)k);
                best = max(best, pk);
            }
        }
        // stage 1: per-warp max
        for (int o = 16; o; o >>= 1)
            best = max(best, __shfl_xor_sync(0xFFFFFFFFu, best, o));
        if ((tid & 31) == 0) swarp[tid >> 5] = best;
        __syncthreads();
        // stage 2: tid0 reduces warps, publishes block partial.
        // Value IS the flag — publish max(m,1) so empty blocks (m==0, e.g.
        // blocks whose key range lies beyond p.M) still release the pollers;
        // the value 1 can never win the argmax (real entries have ~key >> 1).
        if (tid == 0) {
            unsigned long long m = swarp[0];
#pragma unroll
            for (int w = 1; w < NT / 32; w++) m = max(m, swarp[w]);
            *((volatile unsigned long long*)&g_slot[s * NB + b]) = max(m, 1ull);
        }
        __syncthreads();
        // stage 3: poll all block partials (no fence, no atomic counter)
        unsigned long long v = 0ull;
        if (tid < NB) {
            const volatile unsigned long long* sp = &g_slot[s * NB + tid];
            do { v = *sp; } while (v == 0ull);
        }
        for (int o = 16; o; o >>= 1)
            v = max(v, __shfl_xor_sync(0xFFFFFFFFu, v, o));
        if ((tid & 31) == 0) swarp[tid >> 5] = v;
        __syncthreads();
        if (tid == 0) {
            unsigned long long m = swarp[0];
#pragma unroll
            for (int w = 1; w < NT / 32; w++) m = max(m, swarp[w]);
            int nk = (int)(0xFFFFFFFFu - (unsigned)(m & 0xFFFFFFFFull));
            s_last = nk;
            if (b == 0) g_sel[PD + 1 + s] = nk;
        }
        __syncthreads();
        last = s_last;
    }
}

// ---------------- finalize slots: new_index, coords, nums ----------------
__global__ void k_final(const float* vs, const float* cr, float* out, int out_size) {
    int j = blockIdx.x * blockDim.x + threadIdx.x;
    if (j >= MAXV) return;
    P9 p = mkp(vs, cr);
    int key = g_sel[j];
    g_newindex[key] = j;
    int gyz = p.gy * p.gz;
    int ix = key / gyz;
    int r  = key - ix * gyz;
    int iy = r / p.gz;
    int iz = r - iy * p.gz;
    int cbase = MAXV * MAXPTS * 3;
    if (out_size >= cbase + MAXV * 3) {
        out[cbase + 3 * j + 0] = (float)ix;
        out[cbase + 3 * j + 1] = (float)iy;
        out[cbase + 3 * j + 2] = (float)iz;
    }
    int nbase = cbase + MAXV * 3;
    if (out_size >= nbase + MAXV)
        out[nbase + j] = (float)min(g_count[key], MAXPTS);
}

// ---------------- pass 2: collect point indices of selected voxels ----------------
__global__ void k_cpts(int N) {
    int i = blockIdx.x * blockDim.x + threadIdx.x;
    if (i >= N || i >= NMAX) return;
    int k = g_keys[i];
    int s = g_newindex[k];
    if (s >= 0) {
        int pos = atomicAdd(&g_ctr[s], 1);
        if (pos < CAP) g_buf[s * CAP + pos] = i;
    }
}

// ---------------- per-slot: sort indices, emit first min(count,32) points ----------------
__global__ void k_emit(const float* __restrict__ pts, float* out) {
    __shared__ int sb[CAP];
    int s = blockIdx.x, t = threadIdx.x;
    int m = min(g_ctr[s], CAP);
    sb[t] = (t < m) ? g_buf[s * CAP + t] : 0x7FFFFFFF;
    __syncthreads();
    for (int ks = 2; ks <= CAP; ks <<= 1) {
        for (int j = ks >> 1; j > 0; j >>= 1) {
            int ixj = t ^ j;
            if (ixj > t) {
                bool up = ((t & ks) == 0);
                int a = sb[t], c = sb[ixj];
                if ((a > c) == up) { sb[t] = c; sb[ixj] = a; }
            }
            __syncthreads();
        }
    }
    int num = min(m, MAXPTS);
    if (t < num) {
        int idx = sb[t];
        out[(s * MAXPTS + t) * 3 + 0] = pts[3 * idx + 0];
        out[(s * MAXPTS + t) * 3 + 1] = pts[3 * idx + 1];
        out[(s * MAXPTS + t) * 3 + 2] = pts[3 * idx + 2];
    }
}

// ---------------- launch ----------------
extern "C" void kernel_launch(void* const* d_in, const int* in_sizes, int n_in,
                              void* d_out, int out_size) {
    const float* pts = nullptr;
    const float* vs = nullptr;
    const float* cr = nullptr;
    int N = 0;
    for (int i = 0; i < n_in; i++) {
        if (in_sizes[i] == 3) vs = (const float*)d_in[i];
        else if (in_sizes[i] == 6) cr = (const float*)d_in[i];
        else { pts = (const float*)d_in[i]; N = in_sizes[i] / 3; }
    }
    float* out = (float*)d_out;

    cudaMemsetAsync(d_out, 0, (size_t)out_size * sizeof(float), 0);
    int rb = (M_MAX + 255) / 256;
    k_reset<<<rb, 256>>>();
    k_points<<<(N + 255) / 256, 256>>>(pts, vs, cr, N);
    k_hist<<<rb, 256>>>(vs, cr);
    k_thresh<<<1, 1024>>>();
    k_collect<<<rb, 256>>>(vs, cr);
    k_sorttop<<<1, 1024>>>();
    k_prep<<<rb, 256>>>(vs, cr);
    k_fps<<<NB, NT>>>(vs, cr);
    k_final<<<(MAXV + 255) / 256, 256>>>(vs, cr, out, out_size);
    k_cpts<<<(N + 255) / 256, 256>>>(N);
    k_emit<<<MAXV, CAP>>>(pts, out);
}

// round 9
// speedup vs baseline: 1.6877x; 1.6877x over previous
#include <cuda_runtime.h>
#include <math.h>
#include <stdint.h>

#define M_MAX   360448
#define NMAX    8100000
#define PD      614
#define MAXV    1024
#define QFPS    410
#define MAXPTS  32
#define CAP     128
#define LCAP    8192
#define HBINS   2048
#define NB      148
#define NT      256
#define CPT     10      // NB*NT*CPT = 378880 >= M_MAX
#define NSTEPS  (QFPS - 1)

__device__ int                g_count[M_MAX];
__device__ int                g_keys[NMAX];
__device__ int                g_newindex[M_MAX];
__device__ unsigned char      g_valid[M_MAX];
__device__ int                g_hist[HBINS];
__device__ int                g_T;
__device__ unsigned int       g_list[LCAP];
__device__ int                g_listn;
__device__ int                g_sel[MAXV];
__device__ int                g_start;
__device__ unsigned long long g_slot[NSTEPS * NB];   // per-block partials (data-is-flag)
__device__ unsigned long long g_res[NSTEPS];         // per-step winner (data-is-flag)
__device__ int                g_ctr[MAXV];
__device__ int                g_buf[MAXV * CAP];

struct P9 { float lox, loy, loz, vx, vy, vz; int gx, gy, gz, M; };

__device__ __forceinline__ P9 mkp(const float* vs, const float* cr) {
    P9 p;
    p.lox = cr[0]; p.loy = cr[1]; p.loz = cr[2];
    p.vx = vs[0]; p.vy = vs[1]; p.vz = vs[2];
    p.gx = (int)floorf(__fdiv_rn(__fsub_rn(cr[3], cr[0]), vs[0]));
    p.gy = (int)floorf(__fdiv_rn(__fsub_rn(cr[4], cr[1]), vs[1]));
    p.gz = (int)floorf(__fdiv_rn(__fsub_rn(cr[5], cr[2]), vs[2]));
    p.M = p.gx * p.gy * p.gz;
    return p;
}

// centroid: STRICT separate mul + add (locked — bit-exact vs reference)
__device__ __forceinline__ void decode_centroid(int key, const P9& p,
                                                float& cx, float& cy, float& cz) {
    int gyz = p.gy * p.gz;
    int ix = key / gyz;
    int r  = key - ix * gyz;
    int iy = r / p.gz;
    int iz = r - iy * p.gz;
    cx = __fadd_rn(__fmul_rn((float)ix, p.vx), p.lox);
    cy = __fadd_rn(__fmul_rn((float)iy, p.vy), p.loy);
    cz = __fadd_rn(__fmul_rn((float)iz, p.vz), p.loz);
}

// ---------------- reset ----------------
__global__ void k_reset() {
    int i = blockIdx.x * blockDim.x + threadIdx.x;
    if (i < M_MAX) { g_count[i] = 0; g_newindex[i] = -1; }
    if (i < HBINS) g_hist[i] = 0;
    if (i < LCAP)  g_list[i] = 0xFFFFFFFFu;
    if (i < MAXV)  g_ctr[i] = 0;
    if (i < NSTEPS * NB) g_slot[i] = 0ull;
    if (i < NSTEPS) g_res[i] = 0ull;
    if (i == 0) { g_listn = 0; g_start = 0x7FFFFFFF; g_T = 1; }
}

// ---------------- pass 1: keys + histogram ----------------
__global__ void k_points(const float* __restrict__ pts, const float* vs,
                         const float* cr, int N) {
    int i = blockIdx.x * blockDim.x + threadIdx.x;
    if (i >= N || i >= NMAX) return;
    P9 p = mkp(vs, cr);
    float x = pts[3 * i + 0];
    float y = pts[3 * i + 1];
    float z = pts[3 * i + 2];
    int vxi = (int)floorf(__fdiv_rn(__fsub_rn(x, p.lox), p.vx));
    int vyi = (int)floorf(__fdiv_rn(__fsub_rn(y, p.loy), p.vy));
    int vzi = (int)floorf(__fdiv_rn(__fsub_rn(z, p.loz), p.vz));
    vxi = min(max(vxi, 0), p.gx - 1);
    vyi = min(max(vyi, 0), p.gy - 1);
    vzi = min(max(vzi, 0), p.gz - 1);
    int key = (vxi * p.gy + vyi) * p.gz + vzi;
    g_keys[i] = key;
    atomicAdd(&g_count[key], 1);
}

// ---------------- count histogram ----------------
__global__ void k_hist(const float* vs, const float* cr) {
    int k = blockIdx.x * blockDim.x + threadIdx.x;
    P9 p = mkp(vs, cr);
    if (k >= p.M) return;
    int c = g_count[k];
    if (c > 0) atomicAdd(&g_hist[min(c, HBINS - 1)], 1);
}

// ---------------- threshold T: 614th largest count (parallel suffix scan) ----------------
__global__ void k_thresh() {
    int t = threadIdx.x;            // 0..1023, each owns 2 reversed bins
    int c1 = 2047 - 2 * t;          // higher count bin
    int c2 = 2046 - 2 * t;          // lower count bin
    int a0 = g_hist[c1];
    int a1 = (c2 >= 0) ? g_hist[c2] : 0;
    int ts = a0 + a1;
    int lane = t & 31, wid = t >> 5;
    int v = ts;
#pragma unroll
    for (int o = 1; o < 32; o <<= 1) {
        int u = __shfl_up_sync(0xFFFFFFFFu, v, o);
        if (lane >= o) v += u;
    }
    __shared__ int wsum[32];
    if (lane == 31) wsum[wid] = v;
    __syncthreads();
    if (wid == 0) {
        int w = wsum[lane];
#pragma unroll
        for (int o = 1; o < 32; o <<= 1) {
            int u = __shfl_up_sync(0xFFFFFFFFu, w, o);
            if (lane >= o) w += u;
        }
        wsum[lane] = w;
    }
    __syncthreads();
    int incl = v + (wid > 0 ? wsum[wid - 1] : 0);
    int E = incl - ts;              // suffix(c1+1)
    int s1 = E + a0;                // suffix(c1)
    int s2 = E + a0 + a1;           // suffix(c2)
    if (c1 >= 1 && s1 >= PD && E < PD)  g_T = c1;
    if (c2 >= 1 && s2 >= PD && s1 < PD) g_T = c2;
    if (t == 1023 && s1 < PD) g_T = 1;
}

// ---------------- collect keys with count >= T ----------------
__global__ void k_collect(const float* vs, const float* cr) {
    int k = blockIdx.x * blockDim.x + threadIdx.x;
    P9 p = mkp(vs, cr);
    if (k >= p.M) return;
    int c = g_count[k];
    if (c >= g_T) {
        int pos = atomicAdd(&g_listn, 1);
        if (pos < LCAP) {
            unsigned cc = (unsigned)min(c, HBINS - 1);
            g_list[pos] = (((unsigned)(HBINS - 1) - cc) << 19) | (unsigned)k;
        }
    }
}

// ---------------- sort candidates, take top PD in (count desc, key asc) ----------------
__global__ void k_sorttop() {
    __shared__ unsigned int s[LCAP];
    int tid = threadIdx.x;
    for (int t = tid; t < LCAP; t += blockDim.x) s[t] = g_list[t];
    __syncthreads();
    for (int ks = 2; ks <= LCAP; ks <<= 1) {
        for (int j = ks >> 1; j > 0; j >>= 1) {
            for (int t = tid; t < LCAP; t += blockDim.x) {
                int ixj = t ^ j;
                if (ixj > t) {
                    bool up = ((t & ks) == 0);
                    unsigned a = s[t], b = s[ixj];
                    if ((a > b) == up) { s[t] = b; s[ixj] = a; }
                }
            }
            __syncthreads();
        }
    }
    if (tid < PD) {
        int key = (int)(s[tid] & 0x7FFFFu);
        g_sel[tid] = key;
        g_newindex[key] = tid;
    }
}

// ---------------- FPS validity mask + start (smallest remaining key) ----------------
__global__ void k_prep(const float* vs, const float* cr) {
    int k = blockIdx.x * blockDim.x + threadIdx.x;
    P9 p = mkp(vs, cr);
    if (k >= p.M) return;
    int v = (g_count[k] > 0 && g_newindex[k] < 0) ? 1 : 0;
    g_valid[k] = (unsigned char)v;
    if (v) atomicMin(&g_start, k);
}

// ---------------- persistent FPS: hierarchical data-is-flag barrier ----------------
// Level 1: each block writes its partial to g_slot[s][b]    (value IS the flag)
// Level 2: block 0 polls the 148 partials, reduces, writes g_res[s]
// Level 3: other blocks' tid0 polls the single g_res[s] line
__global__ __launch_bounds__(NT) void k_fps(const float* vs, const float* cr) {
    P9 p = mkp(vs, cr);
    int tid = threadIdx.x, b = blockIdx.x;
    int base = b * (NT * CPT);

    float dist[CPT], cx[CPT], cy[CPT], cz[CPT];
    unsigned vm = 0;
#pragma unroll
    for (int j = 0; j < CPT; j++) {
        int k = base + j * NT + tid;
        float X = 0.f, Y = 0.f, Z = 0.f;
        int ok = 0;
        if (k < p.M) {
            ok = g_valid[k];
            decode_centroid(k, p, X, Y, Z);
        }
        cx[j] = X; cy[j] = Y; cz[j] = Z;
        dist[j] = __int_as_float(0x7f800000);  // +inf
        vm |= (ok ? 1u : 0u) << j;
    }

    __shared__ unsigned long long swarp[NT / 32];
    __shared__ int s_last;
    int last = g_start;
    if (b == 0 && tid == 0) g_sel[PD] = g_start;

    for (int s = 0; s < NSTEPS; s++) {
        float lx, ly, lz;
        decode_centroid(last, p, lx, ly, lz);

        unsigned long long best = 0ull;
#pragma unroll
        for (int j = 0; j < CPT; j++) {
            float dx = __fsub_rn(cx[j], lx);
            float dy = __fsub_rn(cy[j], ly);
            float dz = __fsub_rn(cz[j], lz);
            // locked formula: fma(dz,dz, fma(dx,dx, rn(dy*dy)))
            float d = __fmaf_rn(dz, dz, __fmaf_rn(dx, dx, __fmul_rn(dy, dy)));
            float nd = fminf(dist[j], d);
            dist[j] = nd;
            if ((vm >> j) & 1u) {
                int k = base + j * NT + tid;
                unsigned long long pk =
                    ((unsigned long long)__float_as_uint(nd) << 32) |
                    (unsigned long long)(0xFFFFFFFFu - (unsigned)k);
                best = max(best, pk);
            }
        }
        // per-warp max
        for (int o = 16; o; o >>= 1)
            best = max(best, __shfl_xor_sync(0xFFFFFFFFu, best, o));
        if ((tid & 31) == 0) swarp[tid >> 5] = best;
        __syncthreads();
        // publish block partial (max(m,1): empty blocks still release, 1 never wins)
        if (tid == 0) {
            unsigned long long m = swarp[0];
#pragma unroll
            for (int w = 1; w < NT / 32; w++) m = max(m, swarp[w]);
            *((volatile unsigned long long*)&g_slot[s * NB + b]) = max(m, 1ull);
        }

        if (b == 0) {
            // block 0: gather the 148 partials, reduce, publish winner
            unsigned long long v = 0ull;
            if (tid < NB) {
                const volatile unsigned long long* sp = &g_slot[s * NB + tid];
                do { v = *sp; } while (v == 0ull);
            }
            for (int o = 16; o; o >>= 1)
                v = max(v, __shfl_xor_sync(0xFFFFFFFFu, v, o));
            if ((tid & 31) == 0) swarp[tid >> 5] = v;
            __syncthreads();
            if (tid == 0) {
                unsigned long long m = swarp[0];
#pragma unroll
                for (int w = 1; w < NT / 32; w++) m = max(m, swarp[w]);
                int nk = (int)(0xFFFFFFFFu - (unsigned)(m & 0xFFFFFFFFull));
                s_last = nk;
                g_sel[PD + 1 + s] = nk;
                *((volatile unsigned long long*)&g_res[s]) = m;
            }
        } else {
            // other blocks: single thread polls the single result line
            if (tid == 0) {
                const volatile unsigned long long* rp = &g_res[s];
                unsigned long long m;
                do { m = *rp; } while (m == 0ull);
                s_last = (int)(0xFFFFFFFFu - (unsigned)(m & 0xFFFFFFFFull));
            }
        }
        __syncthreads();
        last = s_last;
    }
}

// ---------------- finalize slots: new_index, coords, nums ----------------
__global__ void k_final(const float* vs, const float* cr, float* out, int out_size) {
    int j = blockIdx.x * blockDim.x + threadIdx.x;
    if (j >= MAXV) return;
    P9 p = mkp(vs, cr);
    int key = g_sel[j];
    g_newindex[key] = j;
    int gyz = p.gy * p.gz;
    int ix = key / gyz;
    int r  = key - ix * gyz;
    int iy = r / p.gz;
    int iz = r - iy * p.gz;
    int cbase = MAXV * MAXPTS * 3;
    if (out_size >= cbase + MAXV * 3) {
        out[cbase + 3 * j + 0] = (float)ix;
        out[cbase + 3 * j + 1] = (float)iy;
        out[cbase + 3 * j + 2] = (float)iz;
    }
    int nbase = cbase + MAXV * 3;
    if (out_size >= nbase + MAXV)
        out[nbase + j] = (float)min(g_count[key], MAXPTS);
}

// ---------------- pass 2: collect point indices of selected voxels ----------------
__global__ void k_cpts(int N) {
    int i = blockIdx.x * blockDim.x + threadIdx.x;
    if (i >= N || i >= NMAX) return;
    int k = g_keys[i];
    int s = g_newindex[k];
    if (s >= 0) {
        int pos = atomicAdd(&g_ctr[s], 1);
        if (pos < CAP) g_buf[s * CAP + pos] = i;
    }
}

// ---------------- per-slot: sort indices, emit first min(count,32) points ----------------
__global__ void k_emit(const float* __restrict__ pts, float* out) {
    __shared__ int sb[CAP];
    int s = blockIdx.x, t = threadIdx.x;
    int m = min(g_ctr[s], CAP);
    sb[t] = (t < m) ? g_buf[s * CAP + t] : 0x7FFFFFFF;
    __syncthreads();
    for (int ks = 2; ks <= CAP; ks <<= 1) {
        for (int j = ks >> 1; j > 0; j >>= 1) {
            int ixj = t ^ j;
            if (ixj > t) {
                bool up = ((t & ks) == 0);
                int a = sb[t], c = sb[ixj];
                if ((a > c) == up) { sb[t] = c; sb[ixj] = a; }
            }
            __syncthreads();
        }
    }
    int num = min(m, MAXPTS);
    if (t < num) {
        int idx = sb[t];
        out[(s * MAXPTS + t) * 3 + 0] = pts[3 * idx + 0];
        out[(s * MAXPTS + t) * 3 + 1] = pts[3 * idx + 1];
        out[(s * MAXPTS + t) * 3 + 2] = pts[3 * idx + 2];
    }
}

// ---------------- launch ----------------
extern "C" void kernel_launch(void* const* d_in, const int* in_sizes, int n_in,
                              void* d_out, int out_size) {
    const float* pts = nullptr;
    const float* vs = nullptr;
    const float* cr = nullptr;
    int N = 0;
    for (int i = 0; i < n_in; i++) {
        if (in_sizes[i] == 3) vs = (const float*)d_in[i];
        else if (in_sizes[i] == 6) cr = (const float*)d_in[i];
        else { pts = (const float*)d_in[i]; N = in_sizes[i] / 3; }
    }
    float* out = (float*)d_out;

    cudaMemsetAsync(d_out, 0, (size_t)out_size * sizeof(float), 0);
    int rb = (M_MAX + 255) / 256;
    k_reset<<<rb, 256>>>();
    k_points<<<(N + 255) / 256, 256>>>(pts, vs, cr, N);
    k_hist<<<rb, 256>>>(vs, cr);
    k_thresh<<<1, 1024>>>();
    k_collect<<<rb, 256>>>(vs, cr);
    k_sorttop<<<1, 1024>>>();
    k_prep<<<rb, 256>>>(vs, cr);
    k_fps<<<NB, NT>>>(vs, cr);
    k_final<<<(MAXV + 255) / 256, 256>>>(vs, cr, out, out_size);
    k_cpts<<<(N + 255) / 256, 256>>>(N);
    k_emit<<<MAXV, CAP>>>(pts, out);
}

// round 10
// speedup vs baseline: 2.4745x; 1.4662x over previous
#include <cuda_runtime.h>
#include <math.h>
#include <stdint.h>

#define M_MAX   360448
#define NMAX    8100000
#define PD      614
#define MAXV    1024
#define QFPS    410
#define MAXPTS  32
#define CAP     128
#define LCAP    8192
#define HBINS   2048
#define NB      148
#define NT      256
#define CPT     10      // NB*NT*CPT = 378880 >= M_MAX
#define NSTEPS  (QFPS - 1)
#define RCOPY   8       // result replicas (separate 128B lines)
#define RSTRIDE 16      // u64 stride between replicas = 128B

__device__ int                g_count[M_MAX];
__device__ int                g_keys[NMAX];
__device__ int                g_newindex[M_MAX];
__device__ unsigned char      g_valid[M_MAX];
__device__ int                g_hist[HBINS];
__device__ int                g_T;
__device__ unsigned int       g_list[LCAP];
__device__ int                g_listn;
__device__ int                g_sel[MAXV];
__device__ int                g_start;
__device__ unsigned long long g_slot[NSTEPS * NB];           // per-block partials (data-is-flag)
__device__ unsigned long long g_resN[NSTEPS * RCOPY * RSTRIDE]; // replicated winners
__device__ int                g_ctr[MAXV];
__device__ int                g_buf[MAXV * CAP];

struct P9 { float lox, loy, loz, vx, vy, vz; int gx, gy, gz, M; };

__device__ __forceinline__ P9 mkp(const float* vs, const float* cr) {
    P9 p;
    p.lox = cr[0]; p.loy = cr[1]; p.loz = cr[2];
    p.vx = vs[0]; p.vy = vs[1]; p.vz = vs[2];
    p.gx = (int)floorf(__fdiv_rn(__fsub_rn(cr[3], cr[0]), vs[0]));
    p.gy = (int)floorf(__fdiv_rn(__fsub_rn(cr[4], cr[1]), vs[1]));
    p.gz = (int)floorf(__fdiv_rn(__fsub_rn(cr[5], cr[2]), vs[2]));
    p.M = p.gx * p.gy * p.gz;
    return p;
}

// centroid: STRICT separate mul + add (locked — bit-exact vs reference)
__device__ __forceinline__ void decode_centroid(int key, const P9& p,
                                                float& cx, float& cy, float& cz) {
    int gyz = p.gy * p.gz;
    int ix = key / gyz;
    int r  = key - ix * gyz;
    int iy = r / p.gz;
    int iz = r - iy * p.gz;
    cx = __fadd_rn(__fmul_rn((float)ix, p.vx), p.lox);
    cy = __fadd_rn(__fmul_rn((float)iy, p.vy), p.loy);
    cz = __fadd_rn(__fmul_rn((float)iz, p.vz), p.loz);
}

// pack (dist_bits, key) -> u64 whose nonzero-ness is the ready flag
__device__ __forceinline__ unsigned long long pack_dk(unsigned d, unsigned k) {
    return ((unsigned long long)d << 32) | (unsigned long long)((k << 1) | 1u);
}

// ---------------- reset ----------------
__global__ void k_reset() {
    int i = blockIdx.x * blockDim.x + threadIdx.x;
    if (i < M_MAX) { g_count[i] = 0; g_newindex[i] = -1; }
    if (i < HBINS) g_hist[i] = 0;
    if (i < LCAP)  g_list[i] = 0xFFFFFFFFu;
    if (i < MAXV)  g_ctr[i] = 0;
    if (i < NSTEPS * NB) g_slot[i] = 0ull;
    if (i < NSTEPS * RCOPY * RSTRIDE) g_resN[i] = 0ull;
    if (i == 0) { g_listn = 0; g_start = 0x7FFFFFFF; g_T = 1; }
}

// ---------------- pass 1: keys + histogram ----------------
__global__ void k_points(const float* __restrict__ pts, const float* vs,
                         const float* cr, int N) {
    int i = blockIdx.x * blockDim.x + threadIdx.x;
    if (i >= N || i >= NMAX) return;
    P9 p = mkp(vs, cr);
    float x = pts[3 * i + 0];
    float y = pts[3 * i + 1];
    float z = pts[3 * i + 2];
    int vxi = (int)floorf(__fdiv_rn(__fsub_rn(x, p.lox), p.vx));
    int vyi = (int)floorf(__fdiv_rn(__fsub_rn(y, p.loy), p.vy));
    int vzi = (int)floorf(__fdiv_rn(__fsub_rn(z, p.loz), p.vz));
    vxi = min(max(vxi, 0), p.gx - 1);
    vyi = min(max(vyi, 0), p.gy - 1);
    vzi = min(max(vzi, 0), p.gz - 1);
    int key = (vxi * p.gy + vyi) * p.gz + vzi;
    g_keys[i] = key;
    atomicAdd(&g_count[key], 1);
}

// ---------------- count histogram ----------------
__global__ void k_hist(const float* vs, const float* cr) {
    int k = blockIdx.x * blockDim.x + threadIdx.x;
    P9 p = mkp(vs, cr);
    if (k >= p.M) return;
    int c = g_count[k];
    if (c > 0) atomicAdd(&g_hist[min(c, HBINS - 1)], 1);
}

// ---------------- threshold T: 614th largest count (parallel suffix scan) ----------------
__global__ void k_thresh() {
    int t = threadIdx.x;
    int c1 = 2047 - 2 * t;
    int c2 = 2046 - 2 * t;
    int a0 = g_hist[c1];
    int a1 = (c2 >= 0) ? g_hist[c2] : 0;
    int ts = a0 + a1;
    int lane = t & 31, wid = t >> 5;
    int v = ts;
#pragma unroll
    for (int o = 1; o < 32; o <<= 1) {
        int u = __shfl_up_sync(0xFFFFFFFFu, v, o);
        if (lane >= o) v += u;
    }
    __shared__ int wsum[32];
    if (lane == 31) wsum[wid] = v;
    __syncthreads();
    if (wid == 0) {
        int w = wsum[lane];
#pragma unroll
        for (int o = 1; o < 32; o <<= 1) {
            int u = __shfl_up_sync(0xFFFFFFFFu, w, o);
            if (lane >= o) w += u;
        }
        wsum[lane] = w;
    }
    __syncthreads();
    int incl = v + (wid > 0 ? wsum[wid - 1] : 0);
    int E = incl - ts;
    int s1 = E + a0;
    int s2 = E + a0 + a1;
    if (c1 >= 1 && s1 >= PD && E < PD)  g_T = c1;
    if (c2 >= 1 && s2 >= PD && s1 < PD) g_T = c2;
    if (t == 1023 && s1 < PD) g_T = 1;
}

// ---------------- collect keys with count >= T ----------------
__global__ void k_collect(const float* vs, const float* cr) {
    int k = blockIdx.x * blockDim.x + threadIdx.x;
    P9 p = mkp(vs, cr);
    if (k >= p.M) return;
    int c = g_count[k];
    if (c >= g_T) {
        int pos = atomicAdd(&g_listn, 1);
        if (pos < LCAP) {
            unsigned cc = (unsigned)min(c, HBINS - 1);
            g_list[pos] = (((unsigned)(HBINS - 1) - cc) << 19) | (unsigned)k;
        }
    }
}

// ---------------- sort candidates (dynamic length), top PD (count desc, key asc) ----------------
__global__ void k_sorttop() {
    __shared__ unsigned int s[LCAP];
    int tid = threadIdx.x;
    int n = g_listn;
    int len = (n <= 2048) ? 2048 : LCAP;
    for (int t = tid; t < len; t += blockDim.x) s[t] = g_list[t];
    __syncthreads();
    for (int ks = 2; ks <= len; ks <<= 1) {
        for (int j = ks >> 1; j > 0; j >>= 1) {
            for (int t = tid; t < len; t += blockDim.x) {
                int ixj = t ^ j;
                if (ixj > t) {
                    bool up = ((t & ks) == 0);
                    unsigned a = s[t], b = s[ixj];
                    if ((a > b) == up) { s[t] = b; s[ixj] = a; }
                }
            }
            __syncthreads();
        }
    }
    if (tid < PD) {
        int key = (int)(s[tid] & 0x7FFFFu);
        g_sel[tid] = key;
        g_newindex[key] = tid;
    }
}

// ---------------- FPS validity mask + start (smallest remaining key) ----------------
__global__ void k_prep(const float* vs, const float* cr) {
    int k = blockIdx.x * blockDim.x + threadIdx.x;
    P9 p = mkp(vs, cr);
    if (k >= p.M) return;
    int v = (g_count[k] > 0 && g_newindex[k] < 0) ? 1 : 0;
    g_valid[k] = (unsigned char)v;
    if (v) atomicMin(&g_start, k);
}

// ---------------- persistent FPS: REDUX + replicated-result barrier ----------------
__global__ __launch_bounds__(NT) void k_fps(const float* vs, const float* cr) {
    P9 p = mkp(vs, cr);
    int tid = threadIdx.x, b = blockIdx.x;
    int base = b * (NT * CPT);

    float dist[CPT], cx[CPT], cy[CPT], cz[CPT];
    unsigned vm = 0;
#pragma unroll
    for (int j = 0; j < CPT; j++) {
        int k = base + j * NT + tid;
        float X = 0.f, Y = 0.f, Z = 0.f;
        int ok = 0;
        if (k < p.M) {
            ok = g_valid[k];
            decode_centroid(k, p, X, Y, Z);
        }
        cx[j] = X; cy[j] = Y; cz[j] = Z;
        dist[j] = __int_as_float(0x7f800000);  // +inf
        vm |= (ok ? 1u : 0u) << j;
    }

    __shared__ unsigned long long swarp[8];
    __shared__ int s_last;
    int last = g_start;
    if (b == 0 && tid == 0) g_sel[PD] = g_start;

    for (int s = 0; s < NSTEPS; s++) {
        float lx, ly, lz;
        decode_centroid(last, p, lx, ly, lz);

        unsigned bd = 0u;            // best dist bits (nonneg float: uint cmp == float cmp)
        unsigned bk = 0x7FFFFFFFu;   // best key
#pragma unroll
        for (int j = 0; j < CPT; j++) {
            float dx = __fsub_rn(cx[j], lx);
            float dy = __fsub_rn(cy[j], ly);
            float dz = __fsub_rn(cz[j], lz);
            // locked formula: fma(dz,dz, fma(dx,dx, rn(dy*dy)))
            float d = __fmaf_rn(dz, dz, __fmaf_rn(dx, dx, __fmul_rn(dy, dy)));
            float nd = fminf(dist[j], d);
            dist[j] = nd;
            if ((vm >> j) & 1u) {
                unsigned db = __float_as_uint(nd);
                if (db > bd) { bd = db; bk = (unsigned)(base + j * NT + tid); }
                // strict > : ascending key order => ties keep smallest key
            }
        }
        // warp argmax via REDUX (max dist, then min key among winners)
        unsigned dmax = __reduce_max_sync(0xFFFFFFFFu, bd);
        unsigned kc = (bd == dmax) ? bk : 0x7FFFFFFFu;
        unsigned kmin = __reduce_min_sync(0xFFFFFFFFu, kc);
        if ((tid & 31) == 0) swarp[tid >> 5] = ((unsigned long long)dmax << 32) | kmin;
        __syncthreads();
        // tid0: combine 8 warps, publish block partial (value IS the flag)
        if (tid == 0) {
            unsigned pd = 0u, pk = 0x7FFFFFFFu;
#pragma unroll
            for (int w = 0; w < NT / 32; w++) {
                unsigned long long t = swarp[w];
                unsigned d = (unsigned)(t >> 32), k = (unsigned)t;
                if (d > pd || (d == pd && k < pk)) { pd = d; pk = k; }
            }
            *((volatile unsigned long long*)&g_slot[s * NB + b]) = pack_dk(pd, pk);
        }
        __syncthreads();   // protect swarp reuse below (block 0)

        if (b == 0) {
            // gather 148 partials (5 full warps), backoff polls
            unsigned d = 0u, k = 0x7FFFFFFFu;
            if (tid < 160) {
                if (tid < NB) {
                    const volatile unsigned long long* sp = &g_slot[s * NB + tid];
                    unsigned long long v = *sp;
                    while (v == 0ull) { __nanosleep(40); v = *sp; }
                    d = (unsigned)(v >> 32);
                    k = ((unsigned)v) >> 1;
                }
                unsigned dmax2 = __reduce_max_sync(0xFFFFFFFFu, d);
                unsigned kc2 = (d == dmax2) ? k : 0x7FFFFFFFu;
                unsigned kmin2 = __reduce_min_sync(0xFFFFFFFFu, kc2);
                if ((tid & 31) == 0)
                    swarp[tid >> 5] = ((unsigned long long)dmax2 << 32) | kmin2;
            }
            __syncthreads();
            if (tid == 0) {
                unsigned pd = 0u, pk = 0x7FFFFFFFu;
#pragma unroll
                for (int w = 0; w < 5; w++) {
                    unsigned long long t = swarp[w];
                    unsigned dd = (unsigned)(t >> 32), kk = (unsigned)t;
                    if (dd > pd || (dd == pd && kk < pk)) { pd = dd; pk = kk; }
                }
                s_last = (int)pk;
                g_sel[PD + 1 + s] = (int)pk;
                unsigned long long res = pack_dk(pd, pk);
#pragma unroll
                for (int c = 0; c < RCOPY; c++)
                    *((volatile unsigned long long*)
                          &g_resN[(s * RCOPY + c) * RSTRIDE]) = res;
            }
            __syncthreads();
        } else {
            // one thread polls this block's replica line with backoff
            if (tid == 0) {
                const volatile unsigned long long* rp =
                    &g_resN[(s * RCOPY + (b & (RCOPY - 1))) * RSTRIDE];
                unsigned long long m = *rp;
                while (m == 0ull) { __nanosleep(40); m = *rp; }
                s_last = (int)(((unsigned)m) >> 1);
            }
            __syncthreads();
        }
        last = s_last;
    }
}

// ---------------- finalize slots: new_index, coords, nums ----------------
__global__ void k_final(const float* vs, const float* cr, float* out, int out_size) {
    int j = blockIdx.x * blockDim.x + threadIdx.x;
    if (j >= MAXV) return;
    P9 p = mkp(vs, cr);
    int key = g_sel[j];
    g_newindex[key] = j;
    int gyz = p.gy * p.gz;
    int ix = key / gyz;
    int r  = key - ix * gyz;
    int iy = r / p.gz;
    int iz = r - iy * p.gz;
    int cbase = MAXV * MAXPTS * 3;
    if (out_size >= cbase + MAXV * 3) {
        out[cbase + 3 * j + 0] = (float)ix;
        out[cbase + 3 * j + 1] = (float)iy;
        out[cbase + 3 * j + 2] = (float)iz;
    }
    int nbase = cbase + MAXV * 3;
    if (out_size >= nbase + MAXV)
        out[nbase + j] = (float)min(g_count[key], MAXPTS);
}

// ---------------- pass 2: collect point indices of selected voxels ----------------
__global__ void k_cpts(int N) {
    int i = blockIdx.x * blockDim.x + threadIdx.x;
    if (i >= N || i >= NMAX) return;
    int k = g_keys[i];
    int s = g_newindex[k];
    if (s >= 0) {
        int pos = atomicAdd(&g_ctr[s], 1);
        if (pos < CAP) g_buf[s * CAP + pos] = i;
    }
}

// ---------------- per-slot: sort indices, emit first min(count,32) points ----------------
__global__ void k_emit(const float* __restrict__ pts, float* out) {
    __shared__ int sb[CAP];
    int s = blockIdx.x, t = threadIdx.x;
    int m = min(g_ctr[s], CAP);
    sb[t] = (t < m) ? g_buf[s * CAP + t] : 0x7FFFFFFF;
    __syncthreads();
    for (int ks = 2; ks <= CAP; ks <<= 1) {
        for (int j = ks >> 1; j > 0; j >>= 1) {
            int ixj = t ^ j;
            if (ixj > t) {
                bool up = ((t & ks) == 0);
                int a = sb[t], c = sb[ixj];
                if ((a > c) == up) { sb[t] = c; sb[ixj] = a; }
            }
            __syncthreads();
        }
    }
    int num = min(m, MAXPTS);
    if (t < num) {
        int idx = sb[t];
        out[(s * MAXPTS + t) * 3 + 0] = pts[3 * idx + 0];
        out[(s * MAXPTS + t) * 3 + 1] = pts[3 * idx + 1];
        out[(s * MAXPTS + t) * 3 + 2] = pts[3 * idx + 2];
    }
}

// ---------------- launch ----------------
extern "C" void kernel_launch(void* const* d_in, const int* in_sizes, int n_in,
                              void* d_out, int out_size) {
    const float* pts = nullptr;
    const float* vs = nullptr;
    const float* cr = nullptr;
    int N = 0;
    for (int i = 0; i < n_in; i++) {
        if (in_sizes[i] == 3) vs = (const float*)d_in[i];
        else if (in_sizes[i] == 6) cr = (const float*)d_in[i];
        else { pts = (const float*)d_in[i]; N = in_sizes[i] / 3; }
    }
    float* out = (float*)d_out;

    cudaMemsetAsync(d_out, 0, (size_t)out_size * sizeof(float), 0);
    int rb = (M_MAX + 255) / 256;
    k_reset<<<rb, 256>>>();
    k_points<<<(N + 255) / 256, 256>>>(pts, vs, cr, N);
    k_hist<<<rb, 256>>>(vs, cr);
    k_thresh<<<1, 1024>>>();
    k_collect<<<rb, 256>>>(vs, cr);
    k_sorttop<<<1, 1024>>>();
    k_prep<<<rb, 256>>>(vs, cr);
    k_fps<<<NB, NT>>>(vs, cr);
    k_final<<<(MAXV + 255) / 256, 256>>>(vs, cr, out, out_size);
    k_cpts<<<(N + 255) / 256, 256>>>(N);
    k_emit<<<MAXV, CAP>>>(pts, out);
}